// round 14
// baseline (speedup 1.0000x reference)
#include <cuda_runtime.h>
#include <math.h>

#define NB 64
#define NK 8
#define NV 50257
#define NR (NB*NK)                 // 512 rows
#define OUT_TOK (NB*(NK+1))        // 576
#define FUSED_OFF (OUT_TOK + NB)   // 640

#define GRID (2*NR)                // 1024 CTAs
#define NCPR 16                    // CTAs per batch in stage B
#define CHUNK 3144                 // stage B: NCPR*CHUNK >= NV; smem ~12.6KB
#define ACH 3142                   // stage A chunk: 16*ACH >= NV

// Scratch (device globals: no allocation allowed; zero-initialized)
__device__ float g_part[2*NR*16];  // per-(stream,row,chunk) partial sumexp
__device__ float g_pidx[2*NR];     // exp(logit at draft token) per (stream,row)
__device__ int   g_sel[NB];        // selected flat row index (b*K + rp)
__device__ int   g_fill[NB];       // output slot for recovered token, or -1
__device__ int   g_doneA[NB];      // per-batch stage A unit counter (self-reset)
__device__ int   g_go[NB];         // per-batch A->B release flag
__device__ int   g_cnt2[NB];       // per-batch stage B epilogue counter
// stage B cross-CTA reduction scratch (reset by batch's phase2 leader)
__device__ float              g_sum[NB];
__device__ unsigned long long g_amax[NB];
__device__ int                g_arrive[NB];
__device__ int                g_flag[NB];
__device__ float              g_L[NB];

// monotone float->uint key (total order matching float compare)
__device__ __forceinline__ unsigned int fkey(float f) {
    unsigned int u = __float_as_uint(f);
    return (u & 0x80000000u) ? ~u : (u | 0x80000000u);
}

// ---------------------------------------------------------------------------
// One kernel, 1024 CTAs x 256 threads, all co-resident (8 blocks/SM regs,
// ~13KB smem -> 1184 slots >= 1024), so per-batch spins cannot deadlock.
//
// Stage A (balanced): all valid work flattened into W = 32*sum(num) units
// (batch, k, stream, chunk16); each CTA self-schedules a contiguous ~W/1024
// slice (units ordered by batch -> early batches finish first and pipeline
// into stage B). Each unit: ~12.5KB read, partial sumexp -> g_part slot
// (deterministic: leader sums the 16 partials in fixed order). The unit that
// completes a batch's last unit runs phase2 inline and releases g_go[b].
// Stage B: CTA g serves batch g>>4, chunk g&15 of the selected row; y staged
// in smem; sumexp/argmax combined via atomics; last arriver finalizes.
// ---------------------------------------------------------------------------
__global__ __launch_bounds__(256, 8)
void fused_kernel(const float* __restrict__ tgt,
                  const float* __restrict__ base,
                  const float* __restrict__ steer,
                  const int*   __restrict__ draft,
                  const int*   __restrict__ ndraft,
                  float U, float W_,
                  float* __restrict__ out)
{
    const int TPB = 256;
    const int tid = threadIdx.x;
    const int g   = blockIdx.x;
    const int b_owner = g >> 4;              // batch this CTA serves in stage B

    __shared__ float sy[CHUNK];              // stage B staging
    __shared__ float shs[TPB / 32];
    __shared__ float shm[TPB / 32];
    __shared__ int   shi[TPB / 32];
    __shared__ float sh_L;
    __shared__ int   sh_nd[NB];              // ndraft copy

    if (tid < NB) sh_nd[tid] = ndraft[tid];
    __syncthreads();

    // ======================= Stage A: balanced units =====================
    {
        int total = 0;
        #pragma unroll 8
        for (int b = 0; b < NB; ++b) total += sh_nd[b];
        const int W = 32 * total;            // units: 2 streams * 16 chunks per valid row
        const int lo = (int)(((long long)g       * W) / GRID);
        const int hi = (int)(((long long)(g + 1) * W) / GRID);

        // locate batch containing unit lo
        int bc = 0, bu = 0;                   // bu = first unit index of batch bc
        while (bc < NB && bu + 32 * sh_nd[bc] <= lo) { bu += 32 * sh_nd[bc]; ++bc; }

        for (int u = lo; u < hi; ++u) {
            while (u >= bu + 32 * sh_nd[bc]) { bu += 32 * sh_nd[bc]; ++bc; }
            const int r      = u - bu;
            const int k      = r >> 5;
            const int stream = (r >> 4) & 1;
            const int chunk  = r & 15;
            const int row    = bc * NK + k;
            const size_t roff = (size_t)row * NV;
            const float* __restrict__ src = (stream ? base : tgt) + roff;
            const int c0 = chunk * ACH;
            const int c1 = (c0 + ACH < NV) ? (c0 + ACH) : NV;

            // partial sum of exp over [c0, c1)
            float s0 = 0.f, s1 = 0.f, s2 = 0.f, s3 = 0.f;
            const int pre = (4 - (int)((roff + c0) & 3)) & 3;
            if (tid < pre && c0 + tid < c1) s0 += __expf(src[c0 + tid]);
            const int nvec = (c1 - c0 - pre) >> 2;
            const float4* __restrict__ pv =
                reinterpret_cast<const float4*>(src + c0 + pre);
            #pragma unroll 4
            for (int i = tid; i < nvec; i += TPB) {
                float4 v = pv[i];
                s0 += __expf(v.x); s1 += __expf(v.y);
                s2 += __expf(v.z); s3 += __expf(v.w);
            }
            const int done = c0 + pre + (nvec << 2);
            if (done + tid < c1) s1 += __expf(src[done + tid]);

            float s = (s0 + s1) + (s2 + s3);
            #pragma unroll
            for (int o = 16; o > 0; o >>= 1) s += __shfl_down_sync(0xffffffffu, s, o);
            if ((tid & 31) == 0) shs[tid >> 5] = s;
            __syncthreads();
            if (tid == 0) {
                float tot = 0.f;
                #pragma unroll
                for (int w = 0; w < TPB / 32; ++w) tot += shs[w];
                const int si = stream * NR + row;
                g_part[si * 16 + chunk] = tot;
                const int idx = draft[row];
                if (idx >= c0 && idx < c1) g_pidx[si] = expf(src[idx]);
                __threadfence();
                const int c = atomicAdd(&g_doneA[bc], 1);
                if (c == 32 * sh_nd[bc] - 1) {
                    // ---- leader: phase2 for batch bc ----
                    g_doneA[bc] = 0;               // reset for next replay
                    __threadfence();               // acquire all partials
                    const int num = sh_nd[bc];
                    int cnt = 0;
                    for (int kk = 0; kk < NK; ++kk) {
                        if (kk >= num) break;
                        const int rw = bc * NK + kk;
                        float st = 0.f, sb = 0.f;
                        #pragma unroll
                        for (int cc = 0; cc < 16; ++cc) {
                            st += g_part[(0 * NR + rw) * 16 + cc];
                            sb += g_part[(1 * NR + rw) * 16 + cc];
                        }
                        const float pl = g_pidx[0 * NR + rw] / st;
                        const float pb = g_pidx[1 * NR + rw] / sb;
                        if (!(pl > 0.6f * (pb + 1e-10f))) break;
                        ++cnt;
                    }
                    for (int kk = 0; kk < NK; ++kk)
                        out[bc * (NK + 1) + kk] =
                            (kk < cnt) ? (float)draft[bc * NK + kk] : -1.0f;
                    out[bc * (NK + 1) + NK] = -1.0f;          // bonus (disabled)
                    out[OUT_TOK + bc] = (float)cnt;           // cnt output

                    const int rp = cnt < (NK - 1) ? cnt : (NK - 1);
                    g_sel[bc]  = bc * NK + rp;
                    g_fill[bc] = (cnt < num) ? (bc * (NK + 1) + cnt) : -1;

                    g_sum[bc]    = 0.f;
                    g_amax[bc]   = 0ull;
                    g_arrive[bc] = 0;
                    g_flag[bc]   = 0;
                    __threadfence();
                    atomicExch(&g_go[bc], 1);      // release batch bc
                }
            }
            __syncthreads();                        // shs reuse next unit
        }
    }

    // =================== wait for own batch's release ====================
    if (tid == 0) {
        volatile int* go = &g_go[b_owner];
        while (*go == 0) __nanosleep(32);
    }
    __syncthreads();
    __threadfence();                                // acquire g_sel/g_fill

    // ======================= Stage B: phase3 =============================
    {
        const int b = b_owner;
        const int chunk = g & 15;
        const int row = g_sel[b];
        const int c0 = chunk * CHUNK;
        const int c1 = (c0 + CHUNK < NV) ? (c0 + CHUNK) : NV;
        const size_t rb = (size_t)row * NV;
        const float* __restrict__ pt = tgt   + rb;
        const float* __restrict__ pb = base  + rb;
        const float* __restrict__ ps = steer + rb;

        float m = -INFINITY; int mi = 0; float s = 0.f;

        const int pre = (4 - (int)((rb + c0) & 3)) & 3;
        if (tid < pre && c0 + tid < c1) {
            const int e = c0 + tid;
            float t = pt[e];  if (isnan(t))  t  = -100.f;
            float bb = pb[e]; if (isnan(bb)) bb = -100.f;
            float ss = ps[e]; if (isnan(ss)) ss = -100.f;
            const float y = U * t + W_ * (ss - bb);
            sy[e - c0] = y; s += __expf(y);
            if (y > m) { m = y; mi = e; }
        }

        const int nvec = (c1 - c0 - pre) >> 2;
        const float4* __restrict__ vt = reinterpret_cast<const float4*>(pt + c0 + pre);
        const float4* __restrict__ vb = reinterpret_cast<const float4*>(pb + c0 + pre);
        const float4* __restrict__ vs = reinterpret_cast<const float4*>(ps + c0 + pre);
        #pragma unroll 2
        for (int i = tid; i < nvec; i += TPB) {
            float4 a = vt[i], c = vb[i], d = vs[i];
            if (isnan(a.x)) a.x = -100.f; if (isnan(a.y)) a.y = -100.f;
            if (isnan(a.z)) a.z = -100.f; if (isnan(a.w)) a.w = -100.f;
            if (isnan(c.x)) c.x = -100.f; if (isnan(c.y)) c.y = -100.f;
            if (isnan(c.z)) c.z = -100.f; if (isnan(c.w)) c.w = -100.f;
            if (isnan(d.x)) d.x = -100.f; if (isnan(d.y)) d.y = -100.f;
            if (isnan(d.z)) d.z = -100.f; if (isnan(d.w)) d.w = -100.f;
            const int e = c0 + pre + 4 * i;
            const int l = e - c0;
            const float y0 = U * a.x + W_ * (d.x - c.x);
            const float y1 = U * a.y + W_ * (d.y - c.y);
            const float y2 = U * a.z + W_ * (d.z - c.z);
            const float y3 = U * a.w + W_ * (d.w - c.w);
            sy[l]     = y0; sy[l + 1] = y1;
            sy[l + 2] = y2; sy[l + 3] = y3;
            s += (__expf(y0) + __expf(y1)) + (__expf(y2) + __expf(y3));
            if (y0 > m) { m = y0; mi = e; }
            if (y1 > m) { m = y1; mi = e + 1; }
            if (y2 > m) { m = y2; mi = e + 2; }
            if (y3 > m) { m = y3; mi = e + 3; }
        }
        const int done = c0 + pre + (nvec << 2);
        if (done + tid < c1) {
            const int e = done + tid;
            float t = pt[e];  if (isnan(t))  t  = -100.f;
            float bb = pb[e]; if (isnan(bb)) bb = -100.f;
            float ss = ps[e]; if (isnan(ss)) ss = -100.f;
            const float y = U * t + W_ * (ss - bb);
            sy[e - c0] = y; s += __expf(y);
            if (y > m) { m = y; mi = e; }
        }

        #pragma unroll
        for (int o = 16; o > 0; o >>= 1) {
            s += __shfl_down_sync(0xffffffffu, s, o);
            float m2 = __shfl_down_sync(0xffffffffu, m, o);
            int   i2 = __shfl_down_sync(0xffffffffu, mi, o);
            if (m2 > m || (m2 == m && i2 < mi)) { m = m2; mi = i2; }
        }
        if ((tid & 31) == 0) { shs[tid >> 5] = s; shm[tid >> 5] = m; shi[tid >> 5] = mi; }
        __syncthreads();

        if (tid == 0) {
            float tot = 0.f;
            float M = shm[0]; int MI = shi[0];
            #pragma unroll
            for (int w = 0; w < TPB / 32; ++w) {
                tot += shs[w];
                if (shm[w] > M || (shm[w] == M && shi[w] < MI)) { M = shm[w]; MI = shi[w]; }
            }
            atomicAdd(&g_sum[b], tot);
            const unsigned long long key =
                ((unsigned long long)fkey(M) << 32) |
                (unsigned long long)(0xFFFFFFFFu - (unsigned int)MI);
            atomicMax(&g_amax[b], key);
            __threadfence();
            const int old = atomicAdd(&g_arrive[b], 1);
            if (old == NCPR - 1) {
                const float L = logf(g_sum[b]);
                g_L[b] = L;
                const int f = g_fill[b];
                if (f >= 0) {
                    const unsigned long long kk = g_amax[b];
                    const int idx = (int)(0xFFFFFFFFu - (unsigned int)(kk & 0xFFFFFFFFull));
                    out[f] = (float)idx;            // recovered token
                }
                __threadfence();
                atomicExch(&g_flag[b], 1);
                sh_L = L;
            } else {
                volatile int* fl = &g_flag[b];
                while (*fl == 0) __nanosleep(32);
                __threadfence();
                sh_L = g_L[b];
            }
        }
        __syncthreads();
        const float L = sh_L;

        float* __restrict__ fo = out + FUSED_OFF + (size_t)b * NV;
        for (int i = c0 + tid; i < c1; i += TPB) fo[i] = sy[i - c0] - L;
    }

    // ============== epilogue: reset g_go[b] for graph replay =============
    __threadfence();
    if (tid == 0) {
        const int c = atomicAdd(&g_cnt2[b_owner], 1);
        if (c == NCPR - 1) {
            g_cnt2[b_owner] = 0;
            atomicExch(&g_go[b_owner], 0);
        }
    }
}

// ---------------------------------------------------------------------------
extern "C" void kernel_launch(void* const* d_in, const int* in_sizes, int n_in,
                              void* d_out, int out_size)
{
    const float* tgt    = (const float*)d_in[0];
    const float* base   = (const float*)d_in[1];
    const float* steer  = (const float*)d_in[2];
    const int*   draft  = (const int*)d_in[3];
    const int*   ndraft = (const int*)d_in[4];
    // d_in[5] = bonus_token_ids: unused (ENABLE_BONUS == False)
    float* out = (float*)d_out;

    // Collapse the T=20 costeer recursion to scalar coefficients (double).
    // lp_t = log_softmax(u_t * llm_log + v_t * delta); u_t == 1 exactly.
    double Qu = 0.0, u = 1.0, Qv = 0.0, v = 0.0;
    for (int t = 1; t <= 20; ++t) {
        Qu += 2.0 * (u - 1.0);                 // ALPHA * (u - 1)
        Qv += 2.0 * v + 1.5;                   // ALPHA * v + BETA
        const double denom = 2.0 * t + 0.1;    // t*LAM + 1/ETA
        const double un = (2.0 * t + Qu + u / 10.0) / denom;
        const double vn = (Qv + v / 10.0) / denom;
        u = un; v = vn;
    }
    const float Uf = (float)u;
    const float Wf = (float)v;

    fused_kernel<<<GRID, 256>>>(tgt, base, steer, draft, ndraft, Uf, Wf, out);
}

// round 17
// speedup vs baseline: 1.3674x; 1.3674x over previous
#include <cuda_runtime.h>
#include <math.h>

#define NB 64
#define NK 8
#define NV 50257
#define NR (NB*NK)                 // 512 rows
#define OUT_TOK (NB*(NK+1))        // 576
#define FUSED_OFF (OUT_TOK + NB)   // 640

#define GRID 1024                  // CTAs
#define NCPR 16                    // CTAs per batch in stage B
#define CHUNK 3144                 // stage B: NCPR*CHUNK >= NV; smem ~12.6KB
#define SLOTS 12                   // max covering CTAs per segment (<=9 worst case)

// Scratch (device globals: no allocation allowed; zero-initialized)
__device__ float g_part[1024*SLOTS]; // per-(segment, coverer-rank) partial sumexp
__device__ float g_pidx[2*NR];       // exp(logit at draft token) per (stream,row)
__device__ int   g_sel[NB];          // selected flat row index (b*K + rp)
__device__ int   g_fill[NB];         // output slot for recovered token, or -1
__device__ int   g_doneA[NB];        // per-batch completed-ELEMENT counter (self-reset)
__device__ int   g_go[NB];           // per-batch A->B release flag
__device__ int   g_cnt2[NB];         // per-batch stage B epilogue counter
// stage B cross-CTA reduction scratch (reset by batch's phase2 leader)
__device__ float              g_sum[NB];
__device__ unsigned long long g_amax[NB];
__device__ int                g_arrive[NB];
__device__ int                g_flag[NB];
__device__ float              g_L[NB];

// monotone float->uint key (total order matching float compare)
__device__ __forceinline__ unsigned int fkey(float f) {
    unsigned int u = __float_as_uint(f);
    return (u & 0x80000000u) ? ~u : (u | 0x80000000u);
}

// ---------------------------------------------------------------------------
// One kernel, 1024 CTAs x 256 threads, all co-resident (8 blocks/SM regs,
// ~13KB smem -> 1184 slots >= 1024), so per-batch spins cannot deadlock.
//
// Stage A (balanced, streaming): valid (stream,row) segments (k < num[b])
// flattened batch-major into E = 2*sum(num)*NV elements. CTA g streams the
// contiguous range [g*E/GRID, (g+1)*E/GRID) — ~0.56 row, spanning <=~3
// segments, so <=3 block reductions and NO per-unit barriers inside the
// streaming loops (deep MLP preserved). Partial sums go to deterministic
// slots g_part[seg*SLOTS + (g - gfirst(seg))]; per-batch element counters
// detect the leader, who re-derives the covering-CTA set from the same
// integer formulas, sums slots in fixed order (bitwise deterministic),
// runs phase2, and releases g_go[b]. Early batches pipeline into stage B.
// Stage B: unchanged from R12 (proven): CTA g serves batch g>>4, chunk g&15.
// ---------------------------------------------------------------------------
__global__ __launch_bounds__(256, 8)
void fused_kernel(const float* __restrict__ tgt,
                  const float* __restrict__ basep,
                  const float* __restrict__ steer,
                  const int*   __restrict__ draft,
                  const int*   __restrict__ ndraft,
                  float U, float W_,
                  float* __restrict__ out)
{
    const int TPB = 256;
    const int tid = threadIdx.x;
    const int g   = blockIdx.x;
    const int b_owner = g >> 4;              // batch this CTA serves in stage B

    __shared__ float sy[CHUNK];              // stage B staging
    __shared__ float shs[TPB / 32];
    __shared__ float shm[TPB / 32];
    __shared__ int   shi[TPB / 32];
    __shared__ float sh_L;
    __shared__ int   sh_nd[NB];              // ndraft copy

    if (tid < NB) sh_nd[tid] = ndraft[tid];
    __syncthreads();

    // ======================= Stage A: balanced streaming =================
    {
        int S = 0;
        #pragma unroll 8
        for (int b = 0; b < NB; ++b) S += 2 * sh_nd[b];     // valid segments
        const long long E = (long long)S * NV;
        const long long lo = ((long long)g       * E) / GRID;
        const long long hi = ((long long)(g + 1) * E) / GRID;
        const int sA = (int)(lo / NV);
        const int sB = (int)((hi - 1) / NV);

        // walk to the batch containing segment sA
        int bc = 0, seg_base = 0;
        while (seg_base + 2 * sh_nd[bc] <= sA) { seg_base += 2 * sh_nd[bc]; ++bc; }

        for (int s = sA; s <= sB; ++s) {
            while (s >= seg_base + 2 * sh_nd[bc]) { seg_base += 2 * sh_nd[bc]; ++bc; }
            const int ls     = s - seg_base;
            const int k      = ls >> 1;
            const int stream = ls & 1;
            const int row    = bc * NK + k;
            const size_t roff = (size_t)row * NV;
            const float* __restrict__ src = (stream ? basep : tgt) + roff;

            long long aL = lo - (long long)s * NV; if (aL < 0) aL = 0;
            long long bL = hi - (long long)s * NV; if (bL > NV) bL = NV;
            const int a = (int)aL, bnd = (int)bL;

            // partial sum of exp over [a, bnd) — long contiguous stream
            float s0 = 0.f, s1 = 0.f, s2 = 0.f, s3 = 0.f;
            int pre = (4 - (int)((roff + a) & 3)) & 3;
            if (pre > bnd - a) pre = bnd - a;
            if (tid < pre) s0 += __expf(src[a + tid]);
            const int nvec = (bnd - a - pre) >> 2;
            const float4* __restrict__ pv =
                reinterpret_cast<const float4*>(src + a + pre);
            #pragma unroll 4
            for (int i = tid; i < nvec; i += TPB) {
                float4 v = pv[i];
                s0 += __expf(v.x); s1 += __expf(v.y);
                s2 += __expf(v.z); s3 += __expf(v.w);
            }
            const int done = a + pre + (nvec << 2);
            if (done + tid < bnd) s1 += __expf(src[done + tid]);

            float sacc = (s0 + s1) + (s2 + s3);
            #pragma unroll
            for (int o = 16; o > 0; o >>= 1)
                sacc += __shfl_down_sync(0xffffffffu, sacc, o);
            if ((tid & 31) == 0) shs[tid >> 5] = sacc;
            __syncthreads();

            if (tid == 0) {
                float tot = 0.f;
                #pragma unroll
                for (int w = 0; w < TPB / 32; ++w) tot += shs[w];

                const int gf = (int)(((long long)s * NV * GRID) / E);
                g_part[s * SLOTS + (g - gf)] = tot;
                const int idx = draft[row];
                if (idx >= a && idx < bnd)
                    g_pidx[stream * NR + row] = expf(src[idx]);
                __threadfence();

                const int n   = bnd - a;
                const int tgtN = 2 * sh_nd[bc] * NV;
                const int old = atomicAdd(&g_doneA[bc], n);
                if (old + n == tgtN) {
                    // ---- leader: phase2 for batch bc ----
                    g_doneA[bc] = 0;               // reset for next replay
                    __threadfence();               // acquire all partials
                    const int num = sh_nd[bc];
                    int cnt = 0;
                    for (int kk = 0; kk < num; ++kk) {
                        float sum2[2];
                        #pragma unroll
                        for (int st = 0; st < 2; ++st) {
                            const int ss = seg_base + 2 * kk + st;
                            const int gf2 = (int)(((long long)ss * NV * GRID) / E);
                            const int gl2 = (int)((((long long)(ss + 1) * NV * GRID) - 1) / E);
                            float acc = 0.f;
                            for (int gg = gf2; gg <= gl2; ++gg) {
                                const long long lo_g = ((long long)gg * E) / GRID;
                                const long long hi_g = ((long long)(gg + 1) * E) / GRID;
                                if (lo_g < (long long)(ss + 1) * NV &&
                                    hi_g > (long long)ss * NV)
                                    acc += g_part[ss * SLOTS + (gg - gf2)];
                            }
                            sum2[st] = acc;
                        }
                        const int rw = bc * NK + kk;
                        const float pl = g_pidx[0 * NR + rw] / sum2[0];
                        const float pb = g_pidx[1 * NR + rw] / sum2[1];
                        if (!(pl > 0.6f * (pb + 1e-10f))) break;
                        ++cnt;
                    }
                    for (int kk = 0; kk < NK; ++kk)
                        out[bc * (NK + 1) + kk] =
                            (kk < cnt) ? (float)draft[bc * NK + kk] : -1.0f;
                    out[bc * (NK + 1) + NK] = -1.0f;          // bonus (disabled)
                    out[OUT_TOK + bc] = (float)cnt;           // cnt output

                    const int rp = cnt < (NK - 1) ? cnt : (NK - 1);
                    g_sel[bc]  = bc * NK + rp;
                    g_fill[bc] = (cnt < num) ? (bc * (NK + 1) + cnt) : -1;

                    g_sum[bc]    = 0.f;
                    g_amax[bc]   = 0ull;
                    g_arrive[bc] = 0;
                    g_flag[bc]   = 0;
                    __threadfence();
                    atomicExch(&g_go[bc], 1);      // release batch bc
                }
            }
            __syncthreads();                        // shs reuse next segment
        }
    }

    // =================== wait for own batch's release ====================
    if (tid == 0) {
        volatile int* go = &g_go[b_owner];
        while (*go == 0) __nanosleep(32);
    }
    __syncthreads();
    __threadfence();                                // acquire g_sel/g_fill

    // ======================= Stage B: phase3 =============================
    {
        const int b = b_owner;
        const int chunk = g & 15;
        const int row = g_sel[b];
        const int c0 = chunk * CHUNK;
        const int c1 = (c0 + CHUNK < NV) ? (c0 + CHUNK) : NV;
        const size_t rb = (size_t)row * NV;
        const float* __restrict__ pt = tgt   + rb;
        const float* __restrict__ pb = basep + rb;
        const float* __restrict__ ps = steer + rb;

        float m = -INFINITY; int mi = 0; float s = 0.f;

        const int pre = (4 - (int)((rb + c0) & 3)) & 3;
        if (tid < pre && c0 + tid < c1) {
            const int e = c0 + tid;
            float t = pt[e];  if (isnan(t))  t  = -100.f;
            float bb = pb[e]; if (isnan(bb)) bb = -100.f;
            float ss = ps[e]; if (isnan(ss)) ss = -100.f;
            const float y = U * t + W_ * (ss - bb);
            sy[e - c0] = y; s += __expf(y);
            if (y > m) { m = y; mi = e; }
        }

        const int nvec = (c1 - c0 - pre) >> 2;
        const float4* __restrict__ vt = reinterpret_cast<const float4*>(pt + c0 + pre);
        const float4* __restrict__ vb = reinterpret_cast<const float4*>(pb + c0 + pre);
        const float4* __restrict__ vs = reinterpret_cast<const float4*>(ps + c0 + pre);
        #pragma unroll 2
        for (int i = tid; i < nvec; i += TPB) {
            float4 a = vt[i], c = vb[i], d = vs[i];
            if (isnan(a.x)) a.x = -100.f; if (isnan(a.y)) a.y = -100.f;
            if (isnan(a.z)) a.z = -100.f; if (isnan(a.w)) a.w = -100.f;
            if (isnan(c.x)) c.x = -100.f; if (isnan(c.y)) c.y = -100.f;
            if (isnan(c.z)) c.z = -100.f; if (isnan(c.w)) c.w = -100.f;
            if (isnan(d.x)) d.x = -100.f; if (isnan(d.y)) d.y = -100.f;
            if (isnan(d.z)) d.z = -100.f; if (isnan(d.w)) d.w = -100.f;
            const int e = c0 + pre + 4 * i;
            const int l = e - c0;
            const float y0 = U * a.x + W_ * (d.x - c.x);
            const float y1 = U * a.y + W_ * (d.y - c.y);
            const float y2 = U * a.z + W_ * (d.z - c.z);
            const float y3 = U * a.w + W_ * (d.w - c.w);
            sy[l]     = y0; sy[l + 1] = y1;
            sy[l + 2] = y2; sy[l + 3] = y3;
            s += (__expf(y0) + __expf(y1)) + (__expf(y2) + __expf(y3));
            if (y0 > m) { m = y0; mi = e; }
            if (y1 > m) { m = y1; mi = e + 1; }
            if (y2 > m) { m = y2; mi = e + 2; }
            if (y3 > m) { m = y3; mi = e + 3; }
        }
        const int done = c0 + pre + (nvec << 2);
        if (done + tid < c1) {
            const int e = done + tid;
            float t = pt[e];  if (isnan(t))  t  = -100.f;
            float bb = pb[e]; if (isnan(bb)) bb = -100.f;
            float ss = ps[e]; if (isnan(ss)) ss = -100.f;
            const float y = U * t + W_ * (ss - bb);
            sy[e - c0] = y; s += __expf(y);
            if (y > m) { m = y; mi = e; }
        }

        #pragma unroll
        for (int o = 16; o > 0; o >>= 1) {
            s += __shfl_down_sync(0xffffffffu, s, o);
            float m2 = __shfl_down_sync(0xffffffffu, m, o);
            int   i2 = __shfl_down_sync(0xffffffffu, mi, o);
            if (m2 > m || (m2 == m && i2 < mi)) { m = m2; mi = i2; }
        }
        if ((tid & 31) == 0) { shs[tid >> 5] = s; shm[tid >> 5] = m; shi[tid >> 5] = mi; }
        __syncthreads();

        if (tid == 0) {
            float tot = 0.f;
            float M = shm[0]; int MI = shi[0];
            #pragma unroll
            for (int w = 0; w < TPB / 32; ++w) {
                tot += shs[w];
                if (shm[w] > M || (shm[w] == M && shi[w] < MI)) { M = shm[w]; MI = shi[w]; }
            }
            atomicAdd(&g_sum[b], tot);
            const unsigned long long key =
                ((unsigned long long)fkey(M) << 32) |
                (unsigned long long)(0xFFFFFFFFu - (unsigned int)MI);
            atomicMax(&g_amax[b], key);
            __threadfence();
            const int old = atomicAdd(&g_arrive[b], 1);
            if (old == NCPR - 1) {
                const float L = logf(g_sum[b]);
                g_L[b] = L;
                const int f = g_fill[b];
                if (f >= 0) {
                    const unsigned long long kk = g_amax[b];
                    const int idx = (int)(0xFFFFFFFFu - (unsigned int)(kk & 0xFFFFFFFFull));
                    out[f] = (float)idx;            // recovered token
                }
                __threadfence();
                atomicExch(&g_flag[b], 1);
                sh_L = L;
            } else {
                volatile int* fl = &g_flag[b];
                while (*fl == 0) __nanosleep(32);
                __threadfence();
                sh_L = g_L[b];
            }
        }
        __syncthreads();
        const float L = sh_L;

        float* __restrict__ fo = out + FUSED_OFF + (size_t)b * NV;
        for (int i = c0 + tid; i < c1; i += TPB) fo[i] = sy[i - c0] - L;
    }

    // ============== epilogue: reset g_go[b] for graph replay =============
    __threadfence();
    if (tid == 0) {
        const int c = atomicAdd(&g_cnt2[b_owner], 1);
        if (c == NCPR - 1) {
            g_cnt2[b_owner] = 0;
            atomicExch(&g_go[b_owner], 0);
        }
    }
}

// ---------------------------------------------------------------------------
extern "C" void kernel_launch(void* const* d_in, const int* in_sizes, int n_in,
                              void* d_out, int out_size)
{
    const float* tgt    = (const float*)d_in[0];
    const float* base   = (const float*)d_in[1];
    const float* steer  = (const float*)d_in[2];
    const int*   draft  = (const int*)d_in[3];
    const int*   ndraft = (const int*)d_in[4];
    // d_in[5] = bonus_token_ids: unused (ENABLE_BONUS == False)
    float* out = (float*)d_out;

    // Collapse the T=20 costeer recursion to scalar coefficients (double).
    // lp_t = log_softmax(u_t * llm_log + v_t * delta); u_t == 1 exactly.
    double Qu = 0.0, u = 1.0, Qv = 0.0, v = 0.0;
    for (int t = 1; t <= 20; ++t) {
        Qu += 2.0 * (u - 1.0);                 // ALPHA * (u - 1)
        Qv += 2.0 * v + 1.5;                   // ALPHA * v + BETA
        const double denom = 2.0 * t + 0.1;    // t*LAM + 1/ETA
        const double un = (2.0 * t + Qu + u / 10.0) / denom;
        const double vn = (Qv + v / 10.0) / denom;
        u = un; v = vn;
    }
    const float Uf = (float)u;
    const float Wf = (float)v;

    fused_kernel<<<GRID, 256>>>(tgt, base, steer, draft, ndraft, Uf, Wf, out);
}